// round 14
// baseline (speedup 1.0000x reference)
#include <cuda_runtime.h>
#include <cuda_fp16.h>
#include <cstdint>

#define B_ 2
#define T_ 16
#define N_ 2000
#define F_ 16
#define E_ 32000
#define H_ 4
#define C_ 32
#define D_ 64
#define FF_ 2048
#define G_ (B_*T_)      /* 32  */
#define ET_ (E_+N_)     /* 34000 */
#define BN_ (B_*N_)     /* 4000 */
#define BNP_ (BN_+64)   /* padded rows for 64-row ffn tiles */
#define GN_ (G_*N_)     /* 64000 */

// ---------------- scratch (static device globals; no allocation) -------------
__device__ __half g_h[(size_t)GN_ * 128];  // h: [G,N,H*C] fp16
__device__ float g_asrc[GN_ * 4];
__device__ float g_adst[GN_ * 4];
__device__ float g_prep[8];               // c_edge[0..3], ew_mean at [4]
__device__ int   g_off[N_ + 1];
__device__ int   g_cur[N_];
__device__ int2  g_csr2[ET_];             // packed {src, weight-bits}
__device__ __half g_y[GN_ * D_];          // fp16 [bn][t][d]  (row rn = bn*16+t)
__device__ float g_z[BNP_ * D_];          // post-LN1 (zero-padded tail)
__device__ __half g_wkvh[64 * 128];       // fp16 Wqkv[:,64:192]
__device__ __half g_wqh[64 * 64];         // fp16 Wqkv[:,0:64]
__device__ __half g_woh[64 * 64];         // fp16 Wo
__device__ __half g_w1h[64 * FF_];        // fp16 W1
__device__ __half g_w2h[FF_ * 64];        // fp16 W2
__device__ float g_acc[4][BNP_ * D_];     // ffn split-K planes
__device__ int   g_cnt[64];               // per-row-block completion counters

union HCvt { __half2 h2; uint32_t u; };

// ---------------- mma helpers ------------------------------------------------
__device__ __forceinline__ uint32_t su32(const void* p) {
    uint32_t a;
    asm("{ .reg .u64 t; cvta.to.shared.u64 t, %1; cvt.u32.u64 %0, t; }" : "=r"(a) : "l"(p));
    return a;
}
__device__ __forceinline__ void ldsm_x4(uint32_t& r0, uint32_t& r1, uint32_t& r2, uint32_t& r3, uint32_t a) {
    asm volatile("ldmatrix.sync.aligned.m8n8.x4.shared.b16 {%0,%1,%2,%3}, [%4];"
                 : "=r"(r0), "=r"(r1), "=r"(r2), "=r"(r3) : "r"(a));
}
__device__ __forceinline__ void ldsm_x4t(uint32_t& r0, uint32_t& r1, uint32_t& r2, uint32_t& r3, uint32_t a) {
    asm volatile("ldmatrix.sync.aligned.m8n8.x4.trans.shared.b16 {%0,%1,%2,%3}, [%4];"
                 : "=r"(r0), "=r"(r1), "=r"(r2), "=r"(r3) : "r"(a));
}
__device__ __forceinline__ void mma16816(float* d, uint32_t a0, uint32_t a1, uint32_t a2, uint32_t a3,
                                         uint32_t b0, uint32_t b1) {
    asm volatile("mma.sync.aligned.m16n8k16.row.col.f32.f16.f16.f32 "
                 "{%0,%1,%2,%3}, {%4,%5,%6,%7}, {%8,%9}, {%0,%1,%2,%3};"
                 : "+f"(d[0]), "+f"(d[1]), "+f"(d[2]), "+f"(d[3])
                 : "r"(a0), "r"(a1), "r"(a2), "r"(a3), "r"(b0), "r"(b1));
}

// ---------------- weight conversion to fp16 ----------------------------------
__global__ void k_cvt(const float* __restrict__ Wqkv, const float* __restrict__ W1,
                      const float* __restrict__ W2, const float* __restrict__ Wo) {
    int i = blockIdx.x * 256 + threadIdx.x;
    if (i < 64 * 128) {
        int k = i >> 7, c = i & 127;
        g_wkvh[i] = __float2half(Wqkv[k * 192 + 64 + c]);
    }
    if (i < 64 * 64) {
        int k = i >> 6, c = i & 63;
        g_wqh[i] = __float2half(Wqkv[k * 192 + c]);
        g_woh[i] = __float2half(Wo[i]);
    }
    if (i < 64 * FF_) {
        g_w1h[i] = __float2half(W1[i]);
        g_w2h[i] = __float2half(W2[i]);
    }
}

// ---------------- hist + scan + edge consts (one kernel) ---------------------
__global__ void k_hist(const int* __restrict__ ei, const float* __restrict__ ew,
                       const float* __restrict__ W_edge,
                       const float* __restrict__ att_edge) {
    __shared__ int hist[2048];
    __shared__ float red[1024];
    __shared__ int ws[32];
    int t = threadIdx.x;
    hist[t] = 0; hist[t + 1024] = 0;
    __syncthreads();
    float s = 0.f;
    for (int i = t; i < ET_; i += 1024) {
        int d;
        if (i < E_) { d = ei[E_ + i]; s += ew[i]; }
        else d = i - E_;
        atomicAdd(&hist[d], 1);
    }
    red[t] = s;
    __syncthreads();
    for (int o = 512; o > 0; o >>= 1) {
        if (t < o) red[t] += red[t + o];
        __syncthreads();
    }
    if (t == 0) g_prep[4] = red[0] / (float)E_;
    if (t < 4) {
        float c = 0.f;
        for (int j = 0; j < 32; j++) c += W_edge[t * 32 + j] * att_edge[t * 32 + j];
        g_prep[t] = c;
    }
    int i0 = 2 * t, i1 = 2 * t + 1;
    int a = (i0 < N_) ? hist[i0] : 0;
    int b = (i1 < N_) ? hist[i1] : 0;
    int v = a + b;
    int lane = t & 31, wid = t >> 5;
#pragma unroll
    for (int off = 1; off < 32; off <<= 1) {
        int n = __shfl_up_sync(0xffffffffu, v, off);
        if (lane >= off) v += n;
    }
    if (lane == 31) ws[wid] = v;
    __syncthreads();
    if (t < 32) {
        int u = ws[t];
#pragma unroll
        for (int off = 1; off < 32; off <<= 1) {
            int n = __shfl_up_sync(0xffffffffu, u, off);
            if (t >= off) u += n;
        }
        ws[t] = u;
    }
    __syncthreads();
    int base = (wid > 0) ? ws[wid - 1] : 0;
    int incl = v + base;
    int ex0 = incl - a - b;
    if (i0 <= N_) { g_off[i0] = ex0; if (i0 < N_) g_cur[i0] = ex0; }
    if (i1 <= N_) { g_off[i1] = ex0 + a; if (i1 < N_) g_cur[i1] = ex0 + a; }
}

// ---------------- scatter: pack {src, weight} --------------------------------
__global__ void k_scatter(const int* __restrict__ ei, const float* __restrict__ ew) {
    int e = blockIdx.x * blockDim.x + threadIdx.x;
    if (e >= ET_) return;
    int d, src; float wgt;
    if (e < E_) { src = ei[e]; d = ei[E_ + e]; wgt = ew[e]; }
    else        { src = d = e - E_; wgt = g_prep[4]; }
    int pos = atomicAdd(&g_cur[d], 1);
    g_csr2[pos] = make_int2(src, __float_as_int(wgt));
}

// ---------------- h = x @ W_gat via HMMA (256 rows/block) --------------------
#define XA_ 24
#define XB_ 136
__global__ void __launch_bounds__(256) k_h(const float* __restrict__ x,
                                           const float* __restrict__ Wg,
                                           const float* __restrict__ as_w,
                                           const float* __restrict__ ad_w) {
    __shared__ __half xs[64 * XA_];
    __shared__ __half Bs[16 * XB_];
    __shared__ float s_as[128], s_ad[128];
    int tid = threadIdx.x, wid = tid >> 5, lane = tid & 31;
    for (int i = tid; i < 512; i += 256) {
        int r = i >> 5, c4 = i & 31;
        float4 v = *(const float4*)&Wg[r * 128 + c4 * 4];
        HCvt h0, h1;
        h0.h2 = __floats2half2_rn(v.x, v.y);
        h1.h2 = __floats2half2_rn(v.z, v.w);
        *(uint2*)&Bs[r * XB_ + c4 * 4] = make_uint2(h0.u, h1.u);
    }
    if (tid < 128) { s_as[tid] = as_w[tid]; s_ad[tid] = ad_w[tid]; }
    int mi = wid >> 1;
    int nb = (wid & 1) * 64;
    uint32_t abase = su32(xs) + ((mi * 16 + (lane & 15)) * XA_ + (lane >> 4) * 8) * 2;
    uint32_t bbase = su32(Bs) + (((lane & 15)) * XB_ + nb + (lane >> 4) * 8) * 2;
    int r0 = lane >> 2, c0 = (lane & 3) * 2;
    for (int sub = 0; sub < 4; sub++) {
        int rb = blockIdx.x * 256 + sub * 64;
        __syncthreads();     // prior sub-tile's ldsm reads complete
        for (int i = tid; i < 256; i += 256) {
            int r = i >> 2, s4 = i & 3;
            float4 v = *(const float4*)&x[((size_t)(rb + r)) * 16 + s4 * 4];
            HCvt h0, h1;
            h0.h2 = __floats2half2_rn(v.x, v.y);
            h1.h2 = __floats2half2_rn(v.z, v.w);
            *(uint2*)&xs[r * XA_ + s4 * 4] = make_uint2(h0.u, h1.u);
        }
        __syncthreads();
        float o[4][2][4];
#pragma unroll
        for (int j = 0; j < 4; j++)
#pragma unroll
            for (int n8 = 0; n8 < 2; n8++)
#pragma unroll
                for (int q = 0; q < 4; q++) o[j][n8][q] = 0.f;
        {
            uint32_t a0, a1, a2, a3;
            ldsm_x4(a0, a1, a2, a3, abase);
#pragma unroll
            for (int j = 0; j < 4; j++) {
                uint32_t b0, b1, b2, b3;
                ldsm_x4t(b0, b1, b2, b3, bbase + (j * 16) * 2);
                mma16816(o[j][0], a0, a1, a2, a3, b0, b1);
                mma16816(o[j][1], a0, a1, a2, a3, b2, b3);
            }
        }
        float vs[2][2] = {{0.f, 0.f}, {0.f, 0.f}};
        float vd[2][2] = {{0.f, 0.f}, {0.f, 0.f}};
#pragma unroll
        for (int j = 0; j < 4; j++)
#pragma unroll
            for (int n8 = 0; n8 < 2; n8++) {
                int col = nb + j * 16 + n8 * 8 + c0;
                float a0c = s_as[col], a1c = s_as[col + 1];
                float d0c = s_ad[col], d1c = s_ad[col + 1];
                int hj = j >> 1;
#pragma unroll
                for (int hm = 0; hm < 2; hm++) {
                    float e0 = o[j][n8][hm * 2 + 0];
                    float e1 = o[j][n8][hm * 2 + 1];
                    vs[hm][hj] += e0 * a0c + e1 * a1c;
                    vd[hm][hj] += e0 * d0c + e1 * d1c;
                    int row = rb + mi * 16 + r0 + hm * 8;
                    HCvt v; v.h2 = __floats2half2_rn(e0, e1);
                    *(uint32_t*)&g_h[(size_t)row * 128 + col] = v.u;
                }
            }
#pragma unroll
        for (int hm = 0; hm < 2; hm++)
#pragma unroll
            for (int hj = 0; hj < 2; hj++) {
                vs[hm][hj] += __shfl_xor_sync(0xffffffffu, vs[hm][hj], 1);
                vs[hm][hj] += __shfl_xor_sync(0xffffffffu, vs[hm][hj], 2);
                vd[hm][hj] += __shfl_xor_sync(0xffffffffu, vd[hm][hj], 1);
                vd[hm][hj] += __shfl_xor_sync(0xffffffffu, vd[hm][hj], 2);
            }
        if ((lane & 3) == 0) {
            int hb = (nb >> 5);
#pragma unroll
            for (int hm = 0; hm < 2; hm++) {
                int row = rb + mi * 16 + r0 + hm * 8;
#pragma unroll
                for (int hj = 0; hj < 2; hj++) {
                    g_asrc[(size_t)row * 4 + hb + hj] = vs[hm][hj];
                    g_adst[(size_t)row * 4 + hb + hj] = vd[hm][hj];
                }
            }
        }
    }
}

// ---------------- GAT aggregate v5: csr2 prefetched one full iter ahead ------
__global__ void __launch_bounds__(256) k_agg(const float* __restrict__ gbias,
                                             const float* __restrict__ Wp,
                                             const float* __restrict__ bp) {
    __shared__ float Wps[32 * 64];
    __shared__ float bias_s[32];
    __shared__ float bp_s[64];
    __shared__ float ce_s[4];
    __shared__ float sog[8][32];
    int tid = threadIdx.x;
    for (int i = tid; i < 2048; i += 256) Wps[i] = Wp[i];
    if (tid < 32) bias_s[tid] = gbias[tid];
    if (tid < 64) bp_s[tid] = bp[tid];
    if (tid < 4)  ce_s[tid] = g_prep[tid];
    __syncthreads();
    int wid = tid >> 5;
    int w = blockIdx.x * 8 + wid;
    int lane = tid & 31;
    int grp = lane >> 3;
    int ll = lane & 7;
    int hd = ll >> 1;
    int g = w / N_;
    int dst = w - g * N_;
    float ad = g_adst[((size_t)g * N_ + dst) * 4 + hd];
    float ce = ce_s[hd];
    float acc[16];
#pragma unroll
    for (int j = 0; j < 16; j++) acc[j] = 0.f;
    float den = 0.f;
    int beg = g_off[dst], end = g_off[dst + 1];
    const __half* hbase = g_h + (size_t)g * N_ * 128;
    const float* abase = g_asrc + (size_t)g * N_ * 4;
    int i = beg + grp;
    // pipeline: sw0 = edge for current iter, sw1 = edge for next iter (csr2
    // loaded a full iteration before its dependent asrc/h loads are issued)
    bool v0 = (i < end);
    bool v1 = (i + 4 < end);
    int2 sw0 = v0 ? g_csr2[i] : make_int2(0, 0);
    int2 sw1 = v1 ? g_csr2[i + 4] : make_int2(0, 0);
    int s0i = sw0.x; float w0 = __int_as_float(sw0.y);
    float as0 = abase[s0i * 4 + hd];
    uint4 h00 = *(const uint4*)(hbase + (size_t)s0i * 128 + ll * 16);
    uint4 h01 = *(const uint4*)(hbase + (size_t)s0i * 128 + ll * 16 + 8);
    int cnt = (end - beg + 3) >> 2;
    for (int it = 0; it < cnt; it++) {
        // prefetch csr2 for it+2 (consumed next iteration)
        bool v2 = (i + 8 < end);
        int2 sw2 = v2 ? g_csr2[i + 8] : make_int2(0, 0);
        // issue loads for it+1 from sw1 (resident since last iteration)
        int s1i = sw1.x; float w1 = __int_as_float(sw1.y);
        float as1 = abase[s1i * 4 + hd];
        uint4 h10 = *(const uint4*)(hbase + (size_t)s1i * 128 + ll * 16);
        uint4 h11 = *(const uint4*)(hbase + (size_t)s1i * 128 + ll * 16 + 8);
        // compute current
        float lg = as0 + ad + ce * w0;
        lg = (lg > 0.f) ? lg : 0.2f * lg;
        float p = v0 ? __expf(lg) : 0.f;
        den += p;
        const uint32_t* hw0 = &h00.x;
        const uint32_t* hw1 = &h01.x;
#pragma unroll
        for (int j2 = 0; j2 < 4; j2++) {
            float2 f0 = __half22float2(*(const __half2*)&hw0[j2]);
            float2 f1 = __half22float2(*(const __half2*)&hw1[j2]);
            acc[j2 * 2 + 0] += p * f0.x;
            acc[j2 * 2 + 1] += p * f0.y;
            acc[8 + j2 * 2 + 0] += p * f1.x;
            acc[8 + j2 * 2 + 1] += p * f1.y;
        }
        // rotate
        v0 = v1; w0 = w1; as0 = as1; h00 = h10; h01 = h11;
        sw1 = sw2; v1 = v2;
        i += 4;
    }
    den += __shfl_xor_sync(0xffffffffu, den, 8);
    den += __shfl_xor_sync(0xffffffffu, den, 16);
    float inv = 1.f / (den + 1e-16f);
#pragma unroll
    for (int j = 0; j < 16; j++) {
        acc[j] += __shfl_xor_sync(0xffffffffu, acc[j], 8);
        acc[j] += __shfl_xor_sync(0xffffffffu, acc[j], 16);
        acc[j] *= inv;
        acc[j] += __shfl_xor_sync(0xffffffffu, acc[j], 2);
        acc[j] += __shfl_xor_sync(0xffffffffu, acc[j], 4);
        acc[j] = acc[j] * 0.25f + bias_s[(ll & 1) * 16 + j];
    }
    if (lane < 2) {
#pragma unroll
        for (int j = 0; j < 16; j++) sog[wid][lane * 16 + j] = acc[j];
    }
    __syncwarp();
    int d0 = lane * 2;
    float y0 = bp_s[d0], y1 = bp_s[d0 + 1];
#pragma unroll
    for (int c = 0; c < 32; c++) {
        float vv = sog[wid][c];
        float2 wv = *(const float2*)&Wps[c * 64 + d0];
        y0 += vv * wv.x; y1 += vv * wv.y;
    }
    int b = g >> 4;
    int t = g & 15;
    HCvt yo; yo.h2 = __floats2half2_rn(y0, y1);
    *(uint32_t*)&g_y[(((size_t)(b * N_ + dst)) * T_ + t) * D_ + d0] = yo.u;
}

// ---------------- fused KV-MMA + attention + Wo + residual + LN1 -------------
#define SA_ 72
#define SB_ 136
#define KVP_ 136
__global__ void __launch_bounds__(256) k_attn_fused(const float* __restrict__ bqkv,
                                                    const float* __restrict__ bo,
                                                    const float* __restrict__ ln1g,
                                                    const float* __restrict__ ln1b) {
    __shared__ __half AB[64 * SA_ + 64 * SB_];
    __shared__ float bqs[128];
    __shared__ __half2 Wqs2[64 * 32];
    __shared__ __half2 Wos2[64 * 32];
    __shared__ float bos[64], g1s[64], b1s[64], bq0[64];
    __shared__ float ys[4][64];
    __shared__ float sq[4][64];
    __half* Ah = AB;
    __half* Bs = AB + 64 * SA_;
    __half* KVs = AB;
    int tid = threadIdx.x, wid = tid >> 5, lane = tid & 31;
    int rb = blockIdx.x * 64;
    for (int i = tid; i < 512; i += 256) {
        int r = i >> 3, s = i & 7;
        *(uint4*)&Ah[r * SA_ + s * 8] = *(const uint4*)&g_y[((size_t)(rb + r)) * 64 + s * 8];
    }
    for (int i = tid; i < 1024; i += 256) {
        int r = i >> 4, s = i & 15;
        *(uint4*)&Bs[r * SB_ + s * 8] = *(const uint4*)&g_wkvh[r * 128 + s * 8];
    }
    for (int i = tid; i < 512; i += 256) {
        ((uint4*)Wos2)[i] = ((const uint4*)g_woh)[i];
        ((uint4*)Wqs2)[i] = ((const uint4*)g_wqh)[i];
    }
    if (tid < 128) bqs[tid] = bqkv[64 + tid];
    if (tid < 64) { bos[tid] = bo[tid]; g1s[tid] = ln1g[tid]; b1s[tid] = ln1b[tid]; bq0[tid] = bqkv[tid]; }
    __syncthreads();
    int mi = wid >> 1;
    int nb = (wid & 1) * 64;
    float o[4][2][4];
#pragma unroll
    for (int j = 0; j < 4; j++)
#pragma unroll
        for (int n8 = 0; n8 < 2; n8++)
#pragma unroll
            for (int q = 0; q < 4; q++) o[j][n8][q] = 0.f;
    {
        uint32_t abase = su32(Ah) + ((mi * 16 + (lane & 15)) * SA_ + (lane >> 4) * 8) * 2;
        uint32_t bbase = su32(Bs) + (((lane & 15)) * SB_ + nb + (lane >> 4) * 8) * 2;
#pragma unroll
        for (int k = 0; k < 4; k++) {
            uint32_t a0, a1, a2, a3;
            ldsm_x4(a0, a1, a2, a3, abase + k * 32);
#pragma unroll
            for (int j = 0; j < 4; j++) {
                uint32_t b0, b1, b2, b3;
                ldsm_x4t(b0, b1, b2, b3, bbase + (k * 16 * SB_ + j * 16) * 2);
                mma16816(o[j][0], a0, a1, a2, a3, b0, b1);
                mma16816(o[j][1], a0, a1, a2, a3, b2, b3);
            }
        }
    }
    __syncthreads();
    {
        int r0 = lane >> 2, c0 = (lane & 3) * 2;
#pragma unroll
        for (int j = 0; j < 4; j++)
#pragma unroll
            for (int n8 = 0; n8 < 2; n8++)
#pragma unroll
                for (int hm = 0; hm < 2; hm++) {
                    int row = mi * 16 + r0 + hm * 8;
                    int col = nb + j * 16 + n8 * 8 + c0;
                    HCvt v; v.h2 = __floats2half2_rn(o[j][n8][hm * 2 + 0] + bqs[col],
                                                     o[j][n8][hm * 2 + 1] + bqs[col + 1]);
                    *(uint32_t*)&KVs[row * KVP_ + col] = v.u;
                }
    }
    __syncthreads();
    if (wid >= 4) return;
    int r = blockIdx.x * 4 + wid;
    int lb = wid;
    int dcol = lane * 2;
    __half2 yh = *(const __half2*)&g_y[((size_t)(r * 16 + 15)) * 64 + dcol];
    float2 yv = __half22float2(yh);
    ys[lb][dcol] = yv.x; ys[lb][dcol + 1] = yv.y;
    __syncwarp();
    float q0 = bq0[dcol], q1 = bq0[dcol + 1];
#pragma unroll 16
    for (int j = 0; j < 64; j++) {
        float yj = ys[lb][j];
        float2 wv = __half22float2(Wqs2[j * 32 + lane]);
        q0 += yj * wv.x; q1 += yj * wv.y;
    }
    sq[lb][dcol] = q0; sq[lb][dcol + 1] = q1;
    __syncwarp();
    int t = lane & 15, grp = lane >> 4;
    const __half* kbase = &KVs[(lb * 16 + t) * KVP_ + grp * 32];
    const float* qq = &sq[lb][grp * 32];
    uint4 kr0 = *(const uint4*)&kbase[0];
    uint4 kr1 = *(const uint4*)&kbase[8];
    uint4 kr2 = *(const uint4*)&kbase[16];
    uint4 kr3 = *(const uint4*)&kbase[24];
    float s0 = 0.f, s1 = 0.f;
    {
        const uint32_t* kw0 = &kr0.x;
        const uint32_t* kw1 = &kr1.x;
#pragma unroll
        for (int j2 = 0; j2 < 4; j2++) {
            float2 f0 = __half22float2(*(const __half2*)&kw0[j2]);
            float2 f1 = __half22float2(*(const __half2*)&kw1[j2]);
            s0 += qq[j2 * 2 + 0] * f0.x + qq[j2 * 2 + 1] * f0.y;
            s0 += qq[8 + j2 * 2 + 0] * f1.x + qq[8 + j2 * 2 + 1] * f1.y;
        }
        const uint32_t* kw2 = &kr2.x;
        const uint32_t* kw3 = &kr3.x;
#pragma unroll
        for (int j2 = 0; j2 < 4; j2++) {
            float2 f2 = __half22float2(*(const __half2*)&kw2[j2]);
            float2 f3 = __half22float2(*(const __half2*)&kw3[j2]);
            s1 += qq[16 + j2 * 2 + 0] * f2.x + qq[16 + j2 * 2 + 1] * f2.y;
            s1 += qq[24 + j2 * 2 + 0] * f3.x + qq[24 + j2 * 2 + 1] * f3.y;
        }
    }
    s0 *= 0.25f; s1 *= 0.25f;
    float m0 = s0, m1 = s1;
#pragma unroll
    for (int off = 1; off < 16; off <<= 1) {
        m0 = fmaxf(m0, __shfl_xor_sync(0xffffffffu, m0, off));
        m1 = fmaxf(m1, __shfl_xor_sync(0xffffffffu, m1, off));
    }
    float p0 = __expf(s0 - m0), p1 = __expf(s1 - m1);
    float dn0 = p0, dn1 = p1;
#pragma unroll
    for (int off = 1; off < 16; off <<= 1) {
        dn0 += __shfl_xor_sync(0xffffffffu, dn0, off);
        dn1 += __shfl_xor_sync(0xffffffffu, dn1, off);
    }
    p0 /= dn0; p1 /= dn1;
    int hd = lane >> 3;
    int srcbase = (hd >> 1) * 16;
    int sel = hd & 1;
    float c0v = 0.f, c1v = 0.f;
#pragma unroll
    for (int tt = 0; tt < 16; tt++) {
        float pa = __shfl_sync(0xffffffffu, p0, srcbase + tt);
        float pb = __shfl_sync(0xffffffffu, p1, srcbase + tt);
        float pv = sel ? pb : pa;
        float2 v2 = __half22float2(*(const __half2*)&KVs[(lb * 16 + tt) * KVP_ + 64 + dcol]);
        c0v += pv * v2.x; c1v += pv * v2.y;
    }
    float o0 = bos[dcol], o1 = bos[dcol + 1];
#pragma unroll
    for (int jj = 0; jj < 32; jj++) {
        float ca = __shfl_sync(0xffffffffu, c0v, jj);
        float cb = __shfl_sync(0xffffffffu, c1v, jj);
        float2 wA = __half22float2(Wos2[(2 * jj) * 32 + lane]);
        float2 wB = __half22float2(Wos2[(2 * jj + 1) * 32 + lane]);
        o0 += ca * wA.x + cb * wB.x;
        o1 += ca * wA.y + cb * wB.y;
    }
    float r0v = ys[lb][dcol] + o0, r1v = ys[lb][dcol + 1] + o1;
    float su = r0v + r1v, s2 = r0v * r0v + r1v * r1v;
#pragma unroll
    for (int off = 1; off < 32; off <<= 1) {
        su += __shfl_xor_sync(0xffffffffu, su, off);
        s2 += __shfl_xor_sync(0xffffffffu, s2, off);
    }
    float mu = su * (1.f / 64.f);
    float var = s2 * (1.f / 64.f) - mu * mu;
    float inv = rsqrtf(var + 1e-5f);
    float2 z;
    z.x = (r0v - mu) * inv * g1s[dcol] + b1s[dcol];
    z.y = (r1v - mu) * inv * g1s[dcol + 1] + b1s[dcol + 1];
    *(float2*)&g_z[(size_t)r * 64 + dcol] = z;
}

// ---------------- fused FFN 64-row tiles, split-K(4), LN2 epilogue -----------
__global__ void __launch_bounds__(256) k_ffn(const float* __restrict__ b1,
                                             const float* __restrict__ b2,
                                             const float* __restrict__ ln2g,
                                             const float* __restrict__ ln2b,
                                             float* __restrict__ out) {
    __shared__ __half Ah[64 * SA_];
    __shared__ __half Sh[64 * SA_];
    __shared__ __half W1s[64 * SA_];
    __shared__ __half W2s[64 * SA_];
    __shared__ float b1s[512];
    __shared__ bool last_s;
    int tid = threadIdx.x, wid = tid >> 5, lane = tid & 31;
    int rb = blockIdx.x * 64;
    int kc0 = blockIdx.y * 512;
    for (int i = tid; i < 64 * 16; i += 256) {
        int r = i >> 4, s4 = i & 15;
        float4 v = *(const float4*)&g_z[((size_t)(rb + r)) * 64 + s4 * 4];
        HCvt h0, h1;
        h0.h2 = __floats2half2_rn(v.x, v.y);
        h1.h2 = __floats2half2_rn(v.z, v.w);
        *(uint2*)&Ah[r * SA_ + s4 * 4] = make_uint2(h0.u, h1.u);
    }
    for (int i = tid; i < 512; i += 256) b1s[i] = b1[kc0 + i];
    int mi = wid & 3, nj = wid >> 2;
    float o[2][2][4];
#pragma unroll
    for (int n16 = 0; n16 < 2; n16++)
#pragma unroll
        for (int n8 = 0; n8 < 2; n8++)
#pragma unroll
            for (int q = 0; q < 4; q++) o[n16][n8][q] = 0.f;
    int r0 = lane >> 2, c0 = (lane & 3) * 2;
    uint32_t a1base = su32(Ah) + ((mi * 16 + (lane & 15)) * SA_ + (lane >> 4) * 8) * 2;
    uint32_t a2base = su32(Sh) + ((mi * 16 + (lane & 15)) * SA_ + (lane >> 4) * 8) * 2;
    uint32_t w1base = su32(W1s) + (((lane & 15)) * SA_ + nj * 32 + (lane >> 4) * 8) * 2;
    uint32_t w2base = su32(W2s) + (((lane & 15)) * SA_ + nj * 32 + (lane >> 4) * 8) * 2;
    for (int cb = kc0; cb < kc0 + 512; cb += 64) {
        __syncthreads();
        for (int i = tid; i < 512; i += 256) {
            int r = i >> 3, s = i & 7;
            *(uint4*)&W1s[r * SA_ + s * 8] = *(const uint4*)&g_w1h[(size_t)r * FF_ + cb + s * 8];
            *(uint4*)&W2s[r * SA_ + s * 8] = *(const uint4*)&g_w2h[(size_t)(cb + r) * 64 + s * 8];
        }
        __syncthreads();
        float d[2][2][4];
#pragma unroll
        for (int n16 = 0; n16 < 2; n16++)
#pragma unroll
            for (int n8 = 0; n8 < 2; n8++)
#pragma unroll
                for (int q = 0; q < 4; q++) d[n16][n8][q] = 0.f;
#pragma unroll
        for (int k = 0; k < 4; k++) {
            uint32_t a0, a1, a2, a3, b0v, b1v, b2v, b3v, c0v, c1v, c2v, c3v;
            ldsm_x4(a0, a1, a2, a3, a1base + k * 32);
            ldsm_x4t(b0v, b1v, b2v, b3v, w1base + (k * 16 * SA_) * 2);
            ldsm_x4t(c0v, c1v, c2v, c3v, w1base + (k * 16 * SA_ + 16) * 2);
            mma16816(d[0][0], a0, a1, a2, a3, b0v, b1v);
            mma16816(d[0][1], a0, a1, a2, a3, b2v, b3v);
            mma16816(d[1][0], a0, a1, a2, a3, c0v, c1v);
            mma16816(d[1][1], a0, a1, a2, a3, c2v, c3v);
        }
#pragma unroll
        for (int n16 = 0; n16 < 2; n16++)
#pragma unroll
            for (int n8 = 0; n8 < 2; n8++) {
                int col = nj * 32 + n16 * 16 + n8 * 8 + c0;
                float bb0 = b1s[cb - kc0 + col], bb1 = b1s[cb - kc0 + col + 1];
                HCvt v0, v1;
                v0.h2 = __floats2half2_rn(fmaxf(d[n16][n8][0] + bb0, 0.f), fmaxf(d[n16][n8][1] + bb1, 0.f));
                v1.h2 = __floats2half2_rn(fmaxf(d[n16][n8][2] + bb0, 0.f), fmaxf(d[n16][n8][3] + bb1, 0.f));
                *(uint32_t*)&Sh[(mi * 16 + r0) * SA_ + col] = v0.u;
                *(uint32_t*)&Sh[(mi * 16 + r0 + 8) * SA_ + col] = v1.u;
            }
        __syncthreads();
#pragma unroll
        for (int k = 0; k < 4; k++) {
            uint32_t a0, a1, a2, a3, b0v, b1v, b2v, b3v, c0v, c1v, c2v, c3v;
            ldsm_x4(a0, a1, a2, a3, a2base + k * 32);
            ldsm_x4t(b0v, b1v, b2v, b3v, w2base + (k * 16 * SA_) * 2);
            ldsm_x4t(c0v, c1v, c2v, c3v, w2base + (k * 16 * SA_ + 16) * 2);
            mma16816(o[0][0], a0, a1, a2, a3, b0v, b1v);
            mma16816(o[0][1], a0, a1, a2, a3, b2v, b3v);
            mma16816(o[1][0], a0, a1, a2, a3, c0v, c1v);
            mma16816(o[1][1], a0, a1, a2, a3, c2v, c3v);
        }
    }
    float* plane = g_acc[blockIdx.y];
#pragma unroll
    for (int n16 = 0; n16 < 2; n16++)
#pragma unroll
        for (int n8 = 0; n8 < 2; n8++) {
            int col = nj * 32 + n16 * 16 + n8 * 8 + c0;
            int row = rb + mi * 16 + r0;
            *(float2*)&plane[(size_t)row * 64 + col] = make_float2(o[n16][n8][0], o[n16][n8][1]);
            *(float2*)&plane[(size_t)(row + 8) * 64 + col] = make_float2(o[n16][n8][2], o[n16][n8][3]);
        }
    __threadfence();
    __syncthreads();
    if (tid == 0) {
        int old = atomicAdd(&g_cnt[blockIdx.x], 1);
        last_s = (old == 3);
        if (last_s) g_cnt[blockIdx.x] = 0;
    }
    __syncthreads();
    if (!last_s) return;
    int d2 = lane * 2;
    for (int rr = wid; rr < 64; rr += 8) {
        int r = rb + rr;
        if (r >= BN_) break;
        float2 zr = *(const float2*)&g_z[(size_t)r * 64 + d2];
        float v0 = zr.x + b2[d2];
        float v1 = zr.y + b2[d2 + 1];
#pragma unroll
        for (int pp = 0; pp < 4; pp++) {
            float2 pv = *(const float2*)&g_acc[pp][(size_t)r * 64 + d2];
            v0 += pv.x; v1 += pv.y;
        }
        float su = v0 + v1, s2 = v0 * v0 + v1 * v1;
#pragma unroll
        for (int off = 1; off < 32; off <<= 1) {
            su += __shfl_xor_sync(0xffffffffu, su, off);
            s2 += __shfl_xor_sync(0xffffffffu, s2, off);
        }
        float mu = su * (1.f / 64.f);
        float var = s2 * (1.f / 64.f) - mu * mu;
        float inv = rsqrtf(var + 1e-5f);
        float2 oo;
        oo.x = (v0 - mu) * inv * ln2g[d2] + ln2b[d2];
        oo.y = (v1 - mu) * inv * ln2g[d2 + 1] + ln2b[d2 + 1];
        *(float2*)&out[(size_t)r * 64 + d2] = oo;
    }
}

// ---------------- launch (graph-parallel branches via fork-join) -------------
extern "C" void kernel_launch(void* const* d_in, const int* in_sizes, int n_in,
                              void* d_out, int out_size) {
    const float* x_seq    = (const float*)d_in[0];
    const int*   eidx     = (const int*)d_in[1];
    const float* eweight  = (const float*)d_in[2];
    const float* W_gat    = (const float*)d_in[3];
    const float* att_src  = (const float*)d_in[4];
    const float* att_dst  = (const float*)d_in[5];
    const float* W_edge   = (const float*)d_in[6];
    const float* att_edge = (const float*)d_in[7];
    const float* gat_bias = (const float*)d_in[8];
    const float* W_proj   = (const float*)d_in[9];
    const float* b_proj   = (const float*)d_in[10];
    const float* Wqkv     = (const float*)d_in[11];
    const float* bqkv     = (const float*)d_in[12];
    const float* Wo       = (const float*)d_in[13];
    const float* bo       = (const float*)d_in[14];
    const float* ln1_g    = (const float*)d_in[15];
    const float* ln1_b    = (const float*)d_in[16];
    const float* W1       = (const float*)d_in[17];
    const float* b1       = (const float*)d_in[18];
    const float* W2       = (const float*)d_in[19];
    const float* b2       = (const float*)d_in[20];
    const float* ln2_g    = (const float*)d_in[21];
    const float* ln2_b    = (const float*)d_in[22];
    float* out = (float*)d_out;

    static cudaStream_t sB = nullptr, sC = nullptr;
    static cudaEvent_t evRoot = nullptr, evB = nullptr, evC = nullptr;
    if (sB == nullptr) {
        cudaStreamCreateWithFlags(&sB, cudaStreamNonBlocking);
        cudaStreamCreateWithFlags(&sC, cudaStreamNonBlocking);
        cudaEventCreateWithFlags(&evRoot, cudaEventDisableTiming);
        cudaEventCreateWithFlags(&evB, cudaEventDisableTiming);
        cudaEventCreateWithFlags(&evC, cudaEventDisableTiming);
    }

    cudaEventRecord(evRoot, 0);
    cudaStreamWaitEvent(sB, evRoot, 0);
    cudaStreamWaitEvent(sC, evRoot, 0);

    // branch B: CSR build (feeds k_agg)
    k_hist<<<1, 1024, 0, sB>>>(eidx, eweight, W_edge, att_edge);
    k_scatter<<<(ET_ + 255) / 256, 256, 0, sB>>>(eidx, eweight);
    cudaEventRecord(evB, sB);

    // branch C: fp16 weight conversion
    k_cvt<<<512, 256, 0, sC>>>(Wqkv, W1, W2, Wo);
    cudaEventRecord(evC, sC);

    // main branch: node features via HMMA (256 rows/block)
    k_h<<<GN_ / 256, 256>>>(x_seq, W_gat, att_src, att_dst);

    cudaStreamWaitEvent(0, evB, 0);
    k_agg<<<GN_ / 8, 256>>>(gat_bias, W_proj, b_proj);

    cudaStreamWaitEvent(0, evC, 0);
    k_attn_fused<<<BN_ / 4, 256>>>(bqkv, bo, ln1_g, ln1_b);
    {
        dim3 grid((BN_ + 63) / 64, 4);
        k_ffn<<<grid, 256>>>(b1, b2, ln2_g, ln2_b, out);
    }
}

// round 16
// speedup vs baseline: 1.0300x; 1.0300x over previous
#include <cuda_runtime.h>
#include <cuda_fp16.h>
#include <cstdint>

#define B_ 2
#define T_ 16
#define N_ 2000
#define F_ 16
#define E_ 32000
#define H_ 4
#define C_ 32
#define D_ 64
#define FF_ 2048
#define G_ (B_*T_)      /* 32  */
#define ET_ (E_+N_)     /* 34000 */
#define BN_ (B_*N_)     /* 4000 */
#define BNP_ (BN_+64)   /* padded rows for 64-row ffn tiles */
#define GN_ (G_*N_)     /* 64000 */

// ---------------- scratch (static device globals; no allocation) -------------
__device__ __half g_h[(size_t)GN_ * 128];  // h: [G,N,H*C] fp16
__device__ float g_asrc[GN_ * 4];
__device__ float g_adst[GN_ * 4];
__device__ float g_prep[8];               // c_edge[0..3], ew_mean at [4]
__device__ int   g_off[N_ + 1];
__device__ int   g_cur[N_];
__device__ int2  g_csr2[ET_];             // packed {src, weight-bits}
__device__ __half g_y[GN_ * D_];          // fp16 [bn][t][d]  (row rn = bn*16+t)
__device__ float g_z[BNP_ * D_];          // post-LN1 (zero-padded tail)
__device__ __half g_wkvh[64 * 128];       // fp16 Wqkv[:,64:192]
__device__ __half g_wqh[64 * 64];         // fp16 Wqkv[:,0:64]
__device__ __half g_woh[64 * 64];         // fp16 Wo
__device__ __half g_w1h[64 * FF_];        // fp16 W1
__device__ __half g_w2h[FF_ * 64];        // fp16 W2
__device__ float g_acc[4][BNP_ * D_];     // ffn split-K planes
__device__ int   g_cnt[64];               // per-row-block completion counters

union HCvt { __half2 h2; uint32_t u; };

// ---------------- mma helpers ------------------------------------------------
__device__ __forceinline__ uint32_t su32(const void* p) {
    uint32_t a;
    asm("{ .reg .u64 t; cvta.to.shared.u64 t, %1; cvt.u32.u64 %0, t; }" : "=r"(a) : "l"(p));
    return a;
}
__device__ __forceinline__ void ldsm_x4(uint32_t& r0, uint32_t& r1, uint32_t& r2, uint32_t& r3, uint32_t a) {
    asm volatile("ldmatrix.sync.aligned.m8n8.x4.shared.b16 {%0,%1,%2,%3}, [%4];"
                 : "=r"(r0), "=r"(r1), "=r"(r2), "=r"(r3) : "r"(a));
}
__device__ __forceinline__ void ldsm_x4t(uint32_t& r0, uint32_t& r1, uint32_t& r2, uint32_t& r3, uint32_t a) {
    asm volatile("ldmatrix.sync.aligned.m8n8.x4.trans.shared.b16 {%0,%1,%2,%3}, [%4];"
                 : "=r"(r0), "=r"(r1), "=r"(r2), "=r"(r3) : "r"(a));
}
__device__ __forceinline__ void mma16816(float* d, uint32_t a0, uint32_t a1, uint32_t a2, uint32_t a3,
                                         uint32_t b0, uint32_t b1) {
    asm volatile("mma.sync.aligned.m16n8k16.row.col.f32.f16.f16.f32 "
                 "{%0,%1,%2,%3}, {%4,%5,%6,%7}, {%8,%9}, {%0,%1,%2,%3};"
                 : "+f"(d[0]), "+f"(d[1]), "+f"(d[2]), "+f"(d[3])
                 : "r"(a0), "r"(a1), "r"(a2), "r"(a3), "r"(b0), "r"(b1));
}

// ---------------- weight conversion to fp16 ----------------------------------
__global__ void k_cvt(const float* __restrict__ Wqkv, const float* __restrict__ W1,
                      const float* __restrict__ W2, const float* __restrict__ Wo) {
    int i = blockIdx.x * 256 + threadIdx.x;
    if (i < 64 * 128) {
        int k = i >> 7, c = i & 127;
        g_wkvh[i] = __float2half(Wqkv[k * 192 + 64 + c]);
    }
    if (i < 64 * 64) {
        int k = i >> 6, c = i & 63;
        g_wqh[i] = __float2half(Wqkv[k * 192 + c]);
        g_woh[i] = __float2half(Wo[i]);
    }
    if (i < 64 * FF_) {
        g_w1h[i] = __float2half(W1[i]);
        g_w2h[i] = __float2half(W2[i]);
    }
}

// ---------------- hist + scan + edge consts (one kernel) ---------------------
__global__ void k_hist(const int* __restrict__ ei, const float* __restrict__ ew,
                       const float* __restrict__ W_edge,
                       const float* __restrict__ att_edge) {
    __shared__ int hist[2048];
    __shared__ float red[1024];
    __shared__ int ws[32];
    int t = threadIdx.x;
    hist[t] = 0; hist[t + 1024] = 0;
    __syncthreads();
    float s = 0.f;
    for (int i = t; i < ET_; i += 1024) {
        int d;
        if (i < E_) { d = ei[E_ + i]; s += ew[i]; }
        else d = i - E_;
        atomicAdd(&hist[d], 1);
    }
    red[t] = s;
    __syncthreads();
    for (int o = 512; o > 0; o >>= 1) {
        if (t < o) red[t] += red[t + o];
        __syncthreads();
    }
    if (t == 0) g_prep[4] = red[0] / (float)E_;
    if (t < 4) {
        float c = 0.f;
        for (int j = 0; j < 32; j++) c += W_edge[t * 32 + j] * att_edge[t * 32 + j];
        g_prep[t] = c;
    }
    int i0 = 2 * t, i1 = 2 * t + 1;
    int a = (i0 < N_) ? hist[i0] : 0;
    int b = (i1 < N_) ? hist[i1] : 0;
    int v = a + b;
    int lane = t & 31, wid = t >> 5;
#pragma unroll
    for (int off = 1; off < 32; off <<= 1) {
        int n = __shfl_up_sync(0xffffffffu, v, off);
        if (lane >= off) v += n;
    }
    if (lane == 31) ws[wid] = v;
    __syncthreads();
    if (t < 32) {
        int u = ws[t];
#pragma unroll
        for (int off = 1; off < 32; off <<= 1) {
            int n = __shfl_up_sync(0xffffffffu, u, off);
            if (t >= off) u += n;
        }
        ws[t] = u;
    }
    __syncthreads();
    int base = (wid > 0) ? ws[wid - 1] : 0;
    int incl = v + base;
    int ex0 = incl - a - b;
    if (i0 <= N_) { g_off[i0] = ex0; if (i0 < N_) g_cur[i0] = ex0; }
    if (i1 <= N_) { g_off[i1] = ex0 + a; if (i1 < N_) g_cur[i1] = ex0 + a; }
}

// ---------------- scatter: pack {src, weight} --------------------------------
__global__ void k_scatter(const int* __restrict__ ei, const float* __restrict__ ew) {
    int e = blockIdx.x * blockDim.x + threadIdx.x;
    if (e >= ET_) return;
    int d, src; float wgt;
    if (e < E_) { src = ei[e]; d = ei[E_ + e]; wgt = ew[e]; }
    else        { src = d = e - E_; wgt = g_prep[4]; }
    int pos = atomicAdd(&g_cur[d], 1);
    g_csr2[pos] = make_int2(src, __float_as_int(wgt));
}

// ---------------- h = x @ W_gat via HMMA (64 rows/block) ---------------------
#define XA_ 24
#define XB_ 136
__global__ void __launch_bounds__(256) k_h(const float* __restrict__ x,
                                           const float* __restrict__ Wg,
                                           const float* __restrict__ as_w,
                                           const float* __restrict__ ad_w) {
    __shared__ __half xs[64 * XA_];
    __shared__ __half Bs[16 * XB_];
    __shared__ float s_as[128], s_ad[128];
    int tid = threadIdx.x, wid = tid >> 5, lane = tid & 31;
    int rb = blockIdx.x * 64;
    for (int i = tid; i < 256; i += 256) {
        int r = i >> 2, s4 = i & 3;
        float4 v = *(const float4*)&x[((size_t)(rb + r)) * 16 + s4 * 4];
        HCvt h0, h1;
        h0.h2 = __floats2half2_rn(v.x, v.y);
        h1.h2 = __floats2half2_rn(v.z, v.w);
        *(uint2*)&xs[r * XA_ + s4 * 4] = make_uint2(h0.u, h1.u);
    }
    for (int i = tid; i < 512; i += 256) {
        int r = i >> 5, c4 = i & 31;
        float4 v = *(const float4*)&Wg[r * 128 + c4 * 4];
        HCvt h0, h1;
        h0.h2 = __floats2half2_rn(v.x, v.y);
        h1.h2 = __floats2half2_rn(v.z, v.w);
        *(uint2*)&Bs[r * XB_ + c4 * 4] = make_uint2(h0.u, h1.u);
    }
    if (tid < 128) { s_as[tid] = as_w[tid]; s_ad[tid] = ad_w[tid]; }
    __syncthreads();
    int mi = wid >> 1;
    int nb = (wid & 1) * 64;
    float o[4][2][4];
#pragma unroll
    for (int j = 0; j < 4; j++)
#pragma unroll
        for (int n8 = 0; n8 < 2; n8++)
#pragma unroll
            for (int q = 0; q < 4; q++) o[j][n8][q] = 0.f;
    {
        uint32_t abase = su32(xs) + ((mi * 16 + (lane & 15)) * XA_ + (lane >> 4) * 8) * 2;
        uint32_t bbase = su32(Bs) + (((lane & 15)) * XB_ + nb + (lane >> 4) * 8) * 2;
        uint32_t a0, a1, a2, a3;
        ldsm_x4(a0, a1, a2, a3, abase);
#pragma unroll
        for (int j = 0; j < 4; j++) {
            uint32_t b0, b1, b2, b3;
            ldsm_x4t(b0, b1, b2, b3, bbase + (j * 16) * 2);
            mma16816(o[j][0], a0, a1, a2, a3, b0, b1);
            mma16816(o[j][1], a0, a1, a2, a3, b2, b3);
        }
    }
    int r0 = lane >> 2, c0 = (lane & 3) * 2;
    float vs[2][2] = {{0.f, 0.f}, {0.f, 0.f}};
    float vd[2][2] = {{0.f, 0.f}, {0.f, 0.f}};
#pragma unroll
    for (int j = 0; j < 4; j++)
#pragma unroll
        for (int n8 = 0; n8 < 2; n8++) {
            int col = nb + j * 16 + n8 * 8 + c0;
            float a0c = s_as[col], a1c = s_as[col + 1];
            float d0c = s_ad[col], d1c = s_ad[col + 1];
            int hj = j >> 1;
#pragma unroll
            for (int hm = 0; hm < 2; hm++) {
                float e0 = o[j][n8][hm * 2 + 0];
                float e1 = o[j][n8][hm * 2 + 1];
                vs[hm][hj] += e0 * a0c + e1 * a1c;
                vd[hm][hj] += e0 * d0c + e1 * d1c;
                int row = rb + mi * 16 + r0 + hm * 8;
                HCvt v; v.h2 = __floats2half2_rn(e0, e1);
                *(uint32_t*)&g_h[(size_t)row * 128 + col] = v.u;
            }
        }
#pragma unroll
    for (int hm = 0; hm < 2; hm++)
#pragma unroll
        for (int hj = 0; hj < 2; hj++) {
            vs[hm][hj] += __shfl_xor_sync(0xffffffffu, vs[hm][hj], 1);
            vs[hm][hj] += __shfl_xor_sync(0xffffffffu, vs[hm][hj], 2);
            vd[hm][hj] += __shfl_xor_sync(0xffffffffu, vd[hm][hj], 1);
            vd[hm][hj] += __shfl_xor_sync(0xffffffffu, vd[hm][hj], 2);
        }
    if ((lane & 3) == 0) {
        int hb = (nb >> 5);
#pragma unroll
        for (int hm = 0; hm < 2; hm++) {
            int row = rb + mi * 16 + r0 + hm * 8;
#pragma unroll
            for (int hj = 0; hj < 2; hj++) {
                g_asrc[(size_t)row * 4 + hb + hj] = vs[hm][hj];
                g_adst[(size_t)row * 4 + hb + hj] = vd[hm][hj];
            }
        }
    }
}

// ---------------- GAT aggregate v5: csr2 prefetched one full iter ahead ------
__global__ void __launch_bounds__(256) k_agg(const float* __restrict__ gbias,
                                             const float* __restrict__ Wp,
                                             const float* __restrict__ bp) {
    __shared__ float Wps[32 * 64];
    __shared__ float bias_s[32];
    __shared__ float bp_s[64];
    __shared__ float ce_s[4];
    __shared__ float sog[8][32];
    int tid = threadIdx.x;
    for (int i = tid; i < 2048; i += 256) Wps[i] = Wp[i];
    if (tid < 32) bias_s[tid] = gbias[tid];
    if (tid < 64) bp_s[tid] = bp[tid];
    if (tid < 4)  ce_s[tid] = g_prep[tid];
    __syncthreads();
    int wid = tid >> 5;
    int w = blockIdx.x * 8 + wid;
    int lane = tid & 31;
    int grp = lane >> 3;
    int ll = lane & 7;
    int hd = ll >> 1;
    int g = w / N_;
    int dst = w - g * N_;
    float ad = g_adst[((size_t)g * N_ + dst) * 4 + hd];
    float ce = ce_s[hd];
    float acc[16];
#pragma unroll
    for (int j = 0; j < 16; j++) acc[j] = 0.f;
    float den = 0.f;
    int beg = g_off[dst], end = g_off[dst + 1];
    const __half* hbase = g_h + (size_t)g * N_ * 128;
    const float* abase = g_asrc + (size_t)g * N_ * 4;
    int i = beg + grp;
    bool v0 = (i < end);
    bool v1 = (i + 4 < end);
    int2 sw0 = v0 ? g_csr2[i] : make_int2(0, 0);
    int2 sw1 = v1 ? g_csr2[i + 4] : make_int2(0, 0);
    int s0i = sw0.x; float w0 = __int_as_float(sw0.y);
    float as0 = abase[s0i * 4 + hd];
    uint4 h00 = *(const uint4*)(hbase + (size_t)s0i * 128 + ll * 16);
    uint4 h01 = *(const uint4*)(hbase + (size_t)s0i * 128 + ll * 16 + 8);
    int cnt = (end - beg + 3) >> 2;
    for (int it = 0; it < cnt; it++) {
        bool v2 = (i + 8 < end);
        int2 sw2 = v2 ? g_csr2[i + 8] : make_int2(0, 0);
        int s1i = sw1.x; float w1 = __int_as_float(sw1.y);
        float as1 = abase[s1i * 4 + hd];
        uint4 h10 = *(const uint4*)(hbase + (size_t)s1i * 128 + ll * 16);
        uint4 h11 = *(const uint4*)(hbase + (size_t)s1i * 128 + ll * 16 + 8);
        float lg = as0 + ad + ce * w0;
        lg = (lg > 0.f) ? lg : 0.2f * lg;
        float p = v0 ? __expf(lg) : 0.f;
        den += p;
        const uint32_t* hw0 = &h00.x;
        const uint32_t* hw1 = &h01.x;
#pragma unroll
        for (int j2 = 0; j2 < 4; j2++) {
            float2 f0 = __half22float2(*(const __half2*)&hw0[j2]);
            float2 f1 = __half22float2(*(const __half2*)&hw1[j2]);
            acc[j2 * 2 + 0] += p * f0.x;
            acc[j2 * 2 + 1] += p * f0.y;
            acc[8 + j2 * 2 + 0] += p * f1.x;
            acc[8 + j2 * 2 + 1] += p * f1.y;
        }
        v0 = v1; w0 = w1; as0 = as1; h00 = h10; h01 = h11;
        sw1 = sw2; v1 = v2;
        i += 4;
    }
    den += __shfl_xor_sync(0xffffffffu, den, 8);
    den += __shfl_xor_sync(0xffffffffu, den, 16);
    float inv = 1.f / (den + 1e-16f);
#pragma unroll
    for (int j = 0; j < 16; j++) {
        acc[j] += __shfl_xor_sync(0xffffffffu, acc[j], 8);
        acc[j] += __shfl_xor_sync(0xffffffffu, acc[j], 16);
        acc[j] *= inv;
        acc[j] += __shfl_xor_sync(0xffffffffu, acc[j], 2);
        acc[j] += __shfl_xor_sync(0xffffffffu, acc[j], 4);
        acc[j] = acc[j] * 0.25f + bias_s[(ll & 1) * 16 + j];
    }
    if (lane < 2) {
#pragma unroll
        for (int j = 0; j < 16; j++) sog[wid][lane * 16 + j] = acc[j];
    }
    __syncwarp();
    int d0 = lane * 2;
    float y0 = bp_s[d0], y1 = bp_s[d0 + 1];
#pragma unroll
    for (int c = 0; c < 32; c++) {
        float vv = sog[wid][c];
        float2 wv = *(const float2*)&Wps[c * 64 + d0];
        y0 += vv * wv.x; y1 += vv * wv.y;
    }
    int b = g >> 4;
    int t = g & 15;
    HCvt yo; yo.h2 = __floats2half2_rn(y0, y1);
    *(uint32_t*)&g_y[(((size_t)(b * N_ + dst)) * T_ + t) * D_ + d0] = yo.u;
}

// ---------------- fused KV-MMA + attention + Wo + residual + LN1 -------------
#define SA_ 72
#define SB_ 136
#define KVP_ 136
__global__ void __launch_bounds__(256) k_attn_fused(const float* __restrict__ bqkv,
                                                    const float* __restrict__ bo,
                                                    const float* __restrict__ ln1g,
                                                    const float* __restrict__ ln1b) {
    __shared__ __half AB[64 * SA_ + 64 * SB_];
    __shared__ float bqs[128];
    __shared__ __half2 Wqs2[64 * 32];
    __shared__ __half2 Wos2[64 * 32];
    __shared__ float bos[64], g1s[64], b1s[64], bq0[64];
    __shared__ float ys[4][64];
    __shared__ float sq[4][64];
    __half* Ah = AB;
    __half* Bs = AB + 64 * SA_;
    __half* KVs = AB;
    int tid = threadIdx.x, wid = tid >> 5, lane = tid & 31;
    int rb = blockIdx.x * 64;
    for (int i = tid; i < 512; i += 256) {
        int r = i >> 3, s = i & 7;
        *(uint4*)&Ah[r * SA_ + s * 8] = *(const uint4*)&g_y[((size_t)(rb + r)) * 64 + s * 8];
    }
    for (int i = tid; i < 1024; i += 256) {
        int r = i >> 4, s = i & 15;
        *(uint4*)&Bs[r * SB_ + s * 8] = *(const uint4*)&g_wkvh[r * 128 + s * 8];
    }
    for (int i = tid; i < 512; i += 256) {
        ((uint4*)Wos2)[i] = ((const uint4*)g_woh)[i];
        ((uint4*)Wqs2)[i] = ((const uint4*)g_wqh)[i];
    }
    if (tid < 128) bqs[tid] = bqkv[64 + tid];
    if (tid < 64) { bos[tid] = bo[tid]; g1s[tid] = ln1g[tid]; b1s[tid] = ln1b[tid]; bq0[tid] = bqkv[tid]; }
    __syncthreads();
    int mi = wid >> 1;
    int nb = (wid & 1) * 64;
    float o[4][2][4];
#pragma unroll
    for (int j = 0; j < 4; j++)
#pragma unroll
        for (int n8 = 0; n8 < 2; n8++)
#pragma unroll
            for (int q = 0; q < 4; q++) o[j][n8][q] = 0.f;
    {
        uint32_t abase = su32(Ah) + ((mi * 16 + (lane & 15)) * SA_ + (lane >> 4) * 8) * 2;
        uint32_t bbase = su32(Bs) + (((lane & 15)) * SB_ + nb + (lane >> 4) * 8) * 2;
#pragma unroll
        for (int k = 0; k < 4; k++) {
            uint32_t a0, a1, a2, a3;
            ldsm_x4(a0, a1, a2, a3, abase + k * 32);
#pragma unroll
            for (int j = 0; j < 4; j++) {
                uint32_t b0, b1, b2, b3;
                ldsm_x4t(b0, b1, b2, b3, bbase + (k * 16 * SB_ + j * 16) * 2);
                mma16816(o[j][0], a0, a1, a2, a3, b0, b1);
                mma16816(o[j][1], a0, a1, a2, a3, b2, b3);
            }
        }
    }
    __syncthreads();
    {
        int r0 = lane >> 2, c0 = (lane & 3) * 2;
#pragma unroll
        for (int j = 0; j < 4; j++)
#pragma unroll
            for (int n8 = 0; n8 < 2; n8++)
#pragma unroll
                for (int hm = 0; hm < 2; hm++) {
                    int row = mi * 16 + r0 + hm * 8;
                    int col = nb + j * 16 + n8 * 8 + c0;
                    HCvt v; v.h2 = __floats2half2_rn(o[j][n8][hm * 2 + 0] + bqs[col],
                                                     o[j][n8][hm * 2 + 1] + bqs[col + 1]);
                    *(uint32_t*)&KVs[row * KVP_ + col] = v.u;
                }
    }
    __syncthreads();
    if (wid >= 4) return;
    int r = blockIdx.x * 4 + wid;
    int lb = wid;
    int dcol = lane * 2;
    __half2 yh = *(const __half2*)&g_y[((size_t)(r * 16 + 15)) * 64 + dcol];
    float2 yv = __half22float2(yh);
    ys[lb][dcol] = yv.x; ys[lb][dcol + 1] = yv.y;
    __syncwarp();
    float q0 = bq0[dcol], q1 = bq0[dcol + 1];
#pragma unroll 16
    for (int j = 0; j < 64; j++) {
        float yj = ys[lb][j];
        float2 wv = __half22float2(Wqs2[j * 32 + lane]);
        q0 += yj * wv.x; q1 += yj * wv.y;
    }
    sq[lb][dcol] = q0; sq[lb][dcol + 1] = q1;
    __syncwarp();
    int t = lane & 15, grp = lane >> 4;
    const __half* kbase = &KVs[(lb * 16 + t) * KVP_ + grp * 32];
    const float* qq = &sq[lb][grp * 32];
    uint4 kr0 = *(const uint4*)&kbase[0];
    uint4 kr1 = *(const uint4*)&kbase[8];
    uint4 kr2 = *(const uint4*)&kbase[16];
    uint4 kr3 = *(const uint4*)&kbase[24];
    float s0 = 0.f, s1 = 0.f;
    {
        const uint32_t* kw0 = &kr0.x;
        const uint32_t* kw1 = &kr1.x;
#pragma unroll
        for (int j2 = 0; j2 < 4; j2++) {
            float2 f0 = __half22float2(*(const __half2*)&kw0[j2]);
            float2 f1 = __half22float2(*(const __half2*)&kw1[j2]);
            s0 += qq[j2 * 2 + 0] * f0.x + qq[j2 * 2 + 1] * f0.y;
            s0 += qq[8 + j2 * 2 + 0] * f1.x + qq[8 + j2 * 2 + 1] * f1.y;
        }
        const uint32_t* kw2 = &kr2.x;
        const uint32_t* kw3 = &kr3.x;
#pragma unroll
        for (int j2 = 0; j2 < 4; j2++) {
            float2 f2 = __half22float2(*(const __half2*)&kw2[j2]);
            float2 f3 = __half22float2(*(const __half2*)&kw3[j2]);
            s1 += qq[16 + j2 * 2 + 0] * f2.x + qq[16 + j2 * 2 + 1] * f2.y;
            s1 += qq[24 + j2 * 2 + 0] * f3.x + qq[24 + j2 * 2 + 1] * f3.y;
        }
    }
    s0 *= 0.25f; s1 *= 0.25f;
    float m0 = s0, m1 = s1;
#pragma unroll
    for (int off = 1; off < 16; off <<= 1) {
        m0 = fmaxf(m0, __shfl_xor_sync(0xffffffffu, m0, off));
        m1 = fmaxf(m1, __shfl_xor_sync(0xffffffffu, m1, off));
    }
    float p0 = __expf(s0 - m0), p1 = __expf(s1 - m1);
    float dn0 = p0, dn1 = p1;
#pragma unroll
    for (int off = 1; off < 16; off <<= 1) {
        dn0 += __shfl_xor_sync(0xffffffffu, dn0, off);
        dn1 += __shfl_xor_sync(0xffffffffu, dn1, off);
    }
    p0 /= dn0; p1 /= dn1;
    int hd = lane >> 3;
    int srcbase = (hd >> 1) * 16;
    int sel = hd & 1;
    float c0v = 0.f, c1v = 0.f;
#pragma unroll
    for (int tt = 0; tt < 16; tt++) {
        float pa = __shfl_sync(0xffffffffu, p0, srcbase + tt);
        float pb = __shfl_sync(0xffffffffu, p1, srcbase + tt);
        float pv = sel ? pb : pa;
        float2 v2 = __half22float2(*(const __half2*)&KVs[(lb * 16 + tt) * KVP_ + 64 + dcol]);
        c0v += pv * v2.x; c1v += pv * v2.y;
    }
    float o0 = bos[dcol], o1 = bos[dcol + 1];
#pragma unroll
    for (int jj = 0; jj < 32; jj++) {
        float ca = __shfl_sync(0xffffffffu, c0v, jj);
        float cb = __shfl_sync(0xffffffffu, c1v, jj);
        float2 wA = __half22float2(Wos2[(2 * jj) * 32 + lane]);
        float2 wB = __half22float2(Wos2[(2 * jj + 1) * 32 + lane]);
        o0 += ca * wA.x + cb * wB.x;
        o1 += ca * wA.y + cb * wB.y;
    }
    float r0v = ys[lb][dcol] + o0, r1v = ys[lb][dcol + 1] + o1;
    float su = r0v + r1v, s2 = r0v * r0v + r1v * r1v;
#pragma unroll
    for (int off = 1; off < 32; off <<= 1) {
        su += __shfl_xor_sync(0xffffffffu, su, off);
        s2 += __shfl_xor_sync(0xffffffffu, s2, off);
    }
    float mu = su * (1.f / 64.f);
    float var = s2 * (1.f / 64.f) - mu * mu;
    float inv = rsqrtf(var + 1e-5f);
    float2 z;
    z.x = (r0v - mu) * inv * g1s[dcol] + b1s[dcol];
    z.y = (r1v - mu) * inv * g1s[dcol + 1] + b1s[dcol + 1];
    *(float2*)&g_z[(size_t)r * 64 + dcol] = z;
}

// ---------------- fused FFN 64-row tiles, split-K(4), weight reg-prefetch ----
__global__ void __launch_bounds__(256) k_ffn(const float* __restrict__ b1,
                                             const float* __restrict__ b2,
                                             const float* __restrict__ ln2g,
                                             const float* __restrict__ ln2b,
                                             float* __restrict__ out) {
    __shared__ __half Ah[64 * SA_];
    __shared__ __half Sh[64 * SA_];
    __shared__ __half W1s[64 * SA_];
    __shared__ __half W2s[64 * SA_];
    __shared__ float b1s[512];
    __shared__ bool last_s;
    int tid = threadIdx.x, wid = tid >> 5, lane = tid & 31;
    int rb = blockIdx.x * 64;
    int kc0 = blockIdx.y * 512;
    for (int i = tid; i < 64 * 16; i += 256) {
        int r = i >> 4, s4 = i & 15;
        float4 v = *(const float4*)&g_z[((size_t)(rb + r)) * 64 + s4 * 4];
        HCvt h0, h1;
        h0.h2 = __floats2half2_rn(v.x, v.y);
        h1.h2 = __floats2half2_rn(v.z, v.w);
        *(uint2*)&Ah[r * SA_ + s4 * 4] = make_uint2(h0.u, h1.u);
    }
    for (int i = tid; i < 512; i += 256) b1s[i] = b1[kc0 + i];
    // stage first weight chunk
    {
        int ia = tid, ib = tid + 256;
        int ra = ia >> 3, sa2 = ia & 7, rbx = ib >> 3, sb2 = ib & 7;
        *(uint4*)&W1s[ra * SA_ + sa2 * 8] = *(const uint4*)&g_w1h[(size_t)ra * FF_ + kc0 + sa2 * 8];
        *(uint4*)&W1s[rbx * SA_ + sb2 * 8] = *(const uint4*)&g_w1h[(size_t)rbx * FF_ + kc0 + sb2 * 8];
        *(uint4*)&W2s[ra * SA_ + sa2 * 8] = *(const uint4*)&g_w2h[(size_t)(kc0 + ra) * 64 + sa2 * 8];
        *(uint4*)&W2s[rbx * SA_ + sb2 * 8] = *(const uint4*)&g_w2h[(size_t)(kc0 + rbx) * 64 + sb2 * 8];
    }
    __syncthreads();
    int mi = wid & 3, nj = wid >> 2;
    float o[2][2][4];
#pragma unroll
    for (int n16 = 0; n16 < 2; n16++)
#pragma unroll
        for (int n8 = 0; n8 < 2; n8++)
#pragma unroll
            for (int q = 0; q < 4; q++) o[n16][n8][q] = 0.f;
    int r0 = lane >> 2, c0 = (lane & 3) * 2;
    uint32_t a1base = su32(Ah) + ((mi * 16 + (lane & 15)) * SA_ + (lane >> 4) * 8) * 2;
    uint32_t a2base = su32(Sh) + ((mi * 16 + (lane & 15)) * SA_ + (lane >> 4) * 8) * 2;
    uint32_t w1base = su32(W1s) + (((lane & 15)) * SA_ + nj * 32 + (lane >> 4) * 8) * 2;
    uint32_t w2base = su32(W2s) + (((lane & 15)) * SA_ + nj * 32 + (lane >> 4) * 8) * 2;
    int ia = tid, ib = tid + 256;
    int ra = ia >> 3, sa2 = ia & 7, rbx = ib >> 3, sb2 = ib & 7;
    for (int cb = kc0; cb < kc0 + 512; cb += 64) {
        // register-prefetch next chunk's weights (latency overlapped with MMA)
        bool hn = (cb + 64 < kc0 + 512);
        uint4 p1a, p1b, p2a, p2b;
        if (hn) {
            p1a = *(const uint4*)&g_w1h[(size_t)ra * FF_ + cb + 64 + sa2 * 8];
            p1b = *(const uint4*)&g_w1h[(size_t)rbx * FF_ + cb + 64 + sb2 * 8];
            p2a = *(const uint4*)&g_w2h[(size_t)(cb + 64 + ra) * 64 + sa2 * 8];
            p2b = *(const uint4*)&g_w2h[(size_t)(cb + 64 + rbx) * 64 + sb2 * 8];
        }
        float d[2][2][4];
#pragma unroll
        for (int n16 = 0; n16 < 2; n16++)
#pragma unroll
            for (int n8 = 0; n8 < 2; n8++)
#pragma unroll
                for (int q = 0; q < 4; q++) d[n16][n8][q] = 0.f;
#pragma unroll
        for (int k = 0; k < 4; k++) {
            uint32_t a0, a1, a2, a3, b0v, b1v, b2v, b3v, c0v, c1v, c2v, c3v;
            ldsm_x4(a0, a1, a2, a3, a1base + k * 32);
            ldsm_x4t(b0v, b1v, b2v, b3v, w1base + (k * 16 * SA_) * 2);
            ldsm_x4t(c0v, c1v, c2v, c3v, w1base + (k * 16 * SA_ + 16) * 2);
            mma16816(d[0][0], a0, a1, a2, a3, b0v, b1v);
            mma16816(d[0][1], a0, a1, a2, a3, b2v, b3v);
            mma16816(d[1][0], a0, a1, a2, a3, c0v, c1v);
            mma16816(d[1][1], a0, a1, a2, a3, c2v, c3v);
        }
#pragma unroll
        for (int n16 = 0; n16 < 2; n16++)
#pragma unroll
            for (int n8 = 0; n8 < 2; n8++) {
                int col = nj * 32 + n16 * 16 + n8 * 8 + c0;
                float bb0 = b1s[cb - kc0 + col], bb1 = b1s[cb - kc0 + col + 1];
                HCvt v0, v1;
                v0.h2 = __floats2half2_rn(fmaxf(d[n16][n8][0] + bb0, 0.f), fmaxf(d[n16][n8][1] + bb1, 0.f));
                v1.h2 = __floats2half2_rn(fmaxf(d[n16][n8][2] + bb0, 0.f), fmaxf(d[n16][n8][3] + bb1, 0.f));
                *(uint32_t*)&Sh[(mi * 16 + r0) * SA_ + col] = v0.u;
                *(uint32_t*)&Sh[(mi * 16 + r0 + 8) * SA_ + col] = v1.u;
            }
        __syncthreads();   // Sh visible; W1s reads complete
#pragma unroll
        for (int k = 0; k < 4; k++) {
            uint32_t a0, a1, a2, a3, b0v, b1v, b2v, b3v, c0v, c1v, c2v, c3v;
            ldsm_x4(a0, a1, a2, a3, a2base + k * 32);
            ldsm_x4t(b0v, b1v, b2v, b3v, w2base + (k * 16 * SA_) * 2);
            ldsm_x4t(c0v, c1v, c2v, c3v, w2base + (k * 16 * SA_ + 16) * 2);
            mma16816(o[0][0], a0, a1, a2, a3, b0v, b1v);
            mma16816(o[0][1], a0, a1, a2, a3, b2v, b3v);
            mma16816(o[1][0], a0, a1, a2, a3, c0v, c1v);
            mma16816(o[1][1], a0, a1, a2, a3, c2v, c3v);
        }
        __syncthreads();   // W2s/Sh reads complete
        if (hn) {
            *(uint4*)&W1s[ra * SA_ + sa2 * 8] = p1a;
            *(uint4*)&W1s[rbx * SA_ + sb2 * 8] = p1b;
            *(uint4*)&W2s[ra * SA_ + sa2 * 8] = p2a;
            *(uint4*)&W2s[rbx * SA_ + sb2 * 8] = p2b;
        }
        __syncthreads();   // next chunk staged
    }
    float* plane = g_acc[blockIdx.y];
#pragma unroll
    for (int n16 = 0; n16 < 2; n16++)
#pragma unroll
        for (int n8 = 0; n8 < 2; n8++) {
            int col = nj * 32 + n16 * 16 + n8 * 8 + c0;
            int row = rb + mi * 16 + r0;
            *(float2*)&plane[(size_t)row * 64 + col] = make_float2(o[n16][n8][0], o[n16][n8][1]);
            *(float2*)&plane[(size_t)(row + 8) * 64 + col] = make_float2(o[n16][n8][2], o[n16][n8][3]);
        }
    __threadfence();
    __syncthreads();
    if (tid == 0) {
        int old = atomicAdd(&g_cnt[blockIdx.x], 1);
        last_s = (old == 3);
        if (last_s) g_cnt[blockIdx.x] = 0;
    }
    __syncthreads();
    if (!last_s) return;
    int d2 = lane * 2;
    for (int rr = wid; rr < 64; rr += 8) {
        int r = rb + rr;
        if (r >= BN_) break;
        float2 zr = *(const float2*)&g_z[(size_t)r * 64 + d2];
        float v0 = zr.x + b2[d2];
        float v1 = zr.y + b2[d2 + 1];
#pragma unroll
        for (int pp = 0; pp < 4; pp++) {
            float2 pv = *(const float2*)&g_acc[pp][(size_t)r * 64 + d2];
            v0 += pv.x; v1 += pv.y;
        }
        float su = v0 + v1, s2 = v0 * v0 + v1 * v1;
#pragma unroll
        for (int off = 1; off < 32; off <<= 1) {
            su += __shfl_xor_sync(0xffffffffu, su, off);
            s2 += __shfl_xor_sync(0xffffffffu, s2, off);
        }
        float mu = su * (1.f / 64.f);
        float var = s2 * (1.f / 64.f) - mu * mu;
        float inv = rsqrtf(var + 1e-5f);
        float2 oo;
        oo.x = (v0 - mu) * inv * ln2g[d2] + ln2b[d2];
        oo.y = (v1 - mu) * inv * ln2g[d2 + 1] + ln2b[d2 + 1];
        *(float2*)&out[(size_t)r * 64 + d2] = oo;
    }
}

// ---------------- launch (graph-parallel branches via fork-join) -------------
extern "C" void kernel_launch(void* const* d_in, const int* in_sizes, int n_in,
                              void* d_out, int out_size) {
    const float* x_seq    = (const float*)d_in[0];
    const int*   eidx     = (const int*)d_in[1];
    const float* eweight  = (const float*)d_in[2];
    const float* W_gat    = (const float*)d_in[3];
    const float* att_src  = (const float*)d_in[4];
    const float* att_dst  = (const float*)d_in[5];
    const float* W_edge   = (const float*)d_in[6];
    const float* att_edge = (const float*)d_in[7];
    const float* gat_bias = (const float*)d_in[8];
    const float* W_proj   = (const float*)d_in[9];
    const float* b_proj   = (const float*)d_in[10];
    const float* Wqkv     = (const float*)d_in[11];
    const float* bqkv     = (const float*)d_in[12];
    const float* Wo       = (const float*)d_in[13];
    const float* bo       = (const float*)d_in[14];
    const float* ln1_g    = (const float*)d_in[15];
    const float* ln1_b    = (const float*)d_in[16];
    const float* W1       = (const float*)d_in[17];
    const float* b1       = (const float*)d_in[18];
    const float* W2       = (const float*)d_in[19];
    const float* b2       = (const float*)d_in[20];
    const float* ln2_g    = (const float*)d_in[21];
    const float* ln2_b    = (const float*)d_in[22];
    float* out = (float*)d_out;

    static cudaStream_t sB = nullptr, sC = nullptr;
    static cudaEvent_t evRoot = nullptr, evB = nullptr, evC = nullptr;
    if (sB == nullptr) {
        cudaStreamCreateWithFlags(&sB, cudaStreamNonBlocking);
        cudaStreamCreateWithFlags(&sC, cudaStreamNonBlocking);
        cudaEventCreateWithFlags(&evRoot, cudaEventDisableTiming);
        cudaEventCreateWithFlags(&evB, cudaEventDisableTiming);
        cudaEventCreateWithFlags(&evC, cudaEventDisableTiming);
    }

    cudaEventRecord(evRoot, 0);
    cudaStreamWaitEvent(sB, evRoot, 0);
    cudaStreamWaitEvent(sC, evRoot, 0);

    // branch B: CSR build (feeds k_agg)
    k_hist<<<1, 1024, 0, sB>>>(eidx, eweight, W_edge, att_edge);
    k_scatter<<<(ET_ + 255) / 256, 256, 0, sB>>>(eidx, eweight);
    cudaEventRecord(evB, sB);

    // branch C: fp16 weight conversion
    k_cvt<<<512, 256, 0, sC>>>(Wqkv, W1, W2, Wo);
    cudaEventRecord(evC, sC);

    // main branch: node features via HMMA (64 rows/block)
    k_h<<<GN_ / 64, 256>>>(x_seq, W_gat, att_src, att_dst);

    cudaStreamWaitEvent(0, evB, 0);
    k_agg<<<GN_ / 8, 256>>>(gat_bias, W_proj, b_proj);

    cudaStreamWaitEvent(0, evC, 0);
    k_attn_fused<<<BN_ / 4, 256>>>(bqkv, bo, ln1_g, ln1_b);
    {
        dim3 grid((BN_ + 63) / 64, 4);
        k_ffn<<<grid, 256>>>(b1, b2, ln2_g, ln2_b, out);
    }
}